// round 2
// baseline (speedup 1.0000x reference)
#include <cuda_runtime.h>
#include <cuda_bf16.h>
#include <cstdint>
#include <cstddef>

// Problem dims (fixed by the dataset): x [4,2048,4096] -> M=8192, K=4096; w [16384,4096] -> N=16384
#define MDIM 8192
#define KDIM 4096
#define NDIM 16384
#define MAXV 448.0f
#define EPSV 1e-12f

// ---------------- device scratch (static: allocation-guard safe) ----------------
__device__ unsigned int g_amax_bits[2];     // [0]=x, [1]=w  (float bits, non-negative)
__device__ float g_scales[3];               // [0]=scale_x, [1]=scale_w, [2]=1/(sx*sw)
__device__ __nv_bfloat16 g_xq[(size_t)MDIM * KDIM];   // 64 MB
__device__ __nv_bfloat16 g_wq[(size_t)NDIM * KDIM];   // 128 MB

// ---------------- init ----------------
__global__ void init_kernel() {
    if (threadIdx.x < 2) g_amax_bits[threadIdx.x] = __float_as_uint(EPSV);
}

// ---------------- amax reduction: max(min(|v|,448)) ----------------
__global__ void amax_kernel(const float4* __restrict__ p, size_t n4, int slot) {
    float m = 0.f;
    size_t stride = (size_t)gridDim.x * blockDim.x;
    for (size_t i = (size_t)blockIdx.x * blockDim.x + threadIdx.x; i < n4; i += stride) {
        float4 v = p[i];
        m = fmaxf(m, fminf(fabsf(v.x), MAXV));
        m = fmaxf(m, fminf(fabsf(v.y), MAXV));
        m = fmaxf(m, fminf(fabsf(v.z), MAXV));
        m = fmaxf(m, fminf(fabsf(v.w), MAXV));
    }
#pragma unroll
    for (int o = 16; o > 0; o >>= 1) m = fmaxf(m, __shfl_xor_sync(0xffffffffu, m, o));
    if ((threadIdx.x & 31) == 0) atomicMax(&g_amax_bits[slot], __float_as_uint(m));
}

__global__ void scales_kernel() {
    float ax = __uint_as_float(g_amax_bits[0]);   // >= EPS by init
    float aw = __uint_as_float(g_amax_bits[1]);
    float sx = MAXV / ax, sw = MAXV / aw;
    g_scales[0] = sx;
    g_scales[1] = sw;
    g_scales[2] = (1.f / sx) * (1.f / sw);
}

// ---------------- fake-quantize (scaled domain; result exact in bf16) ----------------
__device__ __forceinline__ float fq1(float v, float scale) {
    float c = fminf(fmaxf(v, -MAXV), MAXV);
    float s = c * scale;                    // |s| <= 448
    float mag = fmaxf(fabsf(s), EPSV);
    int e;
    frexpf(mag, &e);                        // mag = f*2^e, f in [0.5,1)  => floor(log2(mag)) = e-1
    float r = rintf(ldexpf(mag, 4 - e));    // mag/step exactly, in [8,16]; rintf = half-to-even like jnp.round
    float q = ldexpf(r, e - 4);             // r*step exactly
    return copysignf(q, s);
}

__global__ void quant_kernel(const float4* __restrict__ in, size_t n4, int slot) {
    __nv_bfloat16* outq = (slot == 0) ? g_xq : g_wq;
    float s = g_scales[slot];
    size_t stride = (size_t)gridDim.x * blockDim.x;
    for (size_t i = (size_t)blockIdx.x * blockDim.x + threadIdx.x; i < n4; i += stride) {
        float4 v = in[i];
        __nv_bfloat162 lo = __floats2bfloat162_rn(fq1(v.x, s), fq1(v.y, s));
        __nv_bfloat162 hi = __floats2bfloat162_rn(fq1(v.z, s), fq1(v.w, s));
        uint2 pack;
        pack.x = *reinterpret_cast<uint32_t*>(&lo);
        pack.y = *reinterpret_cast<uint32_t*>(&hi);
        *reinterpret_cast<uint2*>(outq + 4 * i) = pack;
    }
}

// ---------------- GEMM: out = (xq @ wq^T) * inv + bias ----------------
#define BM 128
#define BN 128
#define BK 32
#define PITCH 40                 // bf16 units per smem row: 40*2=80B pitch -> conflict-free ldmatrix
#define NKITER (KDIM / BK)       // 128

__device__ __forceinline__ uint32_t smem_u32(const void* p) {
    return (uint32_t)__cvta_generic_to_shared(p);
}
__device__ __forceinline__ void cp16(void* s, const void* g) {
    asm volatile("cp.async.cg.shared.global [%0], [%1], 16;\n" :: "r"(smem_u32(s)), "l"(g));
}
__device__ __forceinline__ void ldsm_x4(uint32_t* r, uint32_t addr) {
    asm volatile("ldmatrix.sync.aligned.m8n8.x4.shared.b16 {%0,%1,%2,%3}, [%4];\n"
                 : "=r"(r[0]), "=r"(r[1]), "=r"(r[2]), "=r"(r[3]) : "r"(addr));
}
__device__ __forceinline__ void mma16816(float* c, const uint32_t* a, const uint32_t* b) {
    asm volatile("mma.sync.aligned.m16n8k16.row.col.f32.bf16.bf16.f32 "
                 "{%0,%1,%2,%3}, {%4,%5,%6,%7}, {%8,%9}, {%0,%1,%2,%3};\n"
                 : "+f"(c[0]), "+f"(c[1]), "+f"(c[2]), "+f"(c[3])
                 : "r"(a[0]), "r"(a[1]), "r"(a[2]), "r"(a[3]), "r"(b[0]), "r"(b[1]));
}

__device__ __forceinline__ void load_stage(
    __nv_bfloat16* sA, __nv_bfloat16* sB,
    const __nv_bfloat16* __restrict__ gA, const __nv_bfloat16* __restrict__ gB,
    int k0, int tid)
{
#pragma unroll
    for (int it = 0; it < 2; ++it) {
        int chunk = tid + it * 256;          // 512 chunks of 16B per operand
        int row = chunk >> 2;
        int c = (chunk & 3) * 8;             // bf16 units
        cp16(&sA[row * PITCH + c], gA + (size_t)row * KDIM + k0 + c);
        cp16(&sB[row * PITCH + c], gB + (size_t)row * KDIM + k0 + c);
    }
    asm volatile("cp.async.commit_group;\n" ::: "memory");
}

__global__ __launch_bounds__(256) void gemm_kernel(const float* __restrict__ bias,
                                                   float* __restrict__ out) {
    __shared__ __nv_bfloat16 sA[2][BM * PITCH];   // 2*10240 B
    __shared__ __nv_bfloat16 sB[2][BN * PITCH];   // 2*10240 B  (total 40 KB)

    int tid = threadIdx.x;
    int lane = tid & 31, warp = tid >> 5;
    int wm = (warp >> 2) * 64;   // warp tile: 64(M) x 32(N); warps 2x4
    int wn = (warp & 3) * 32;

    const __nv_bfloat16* gA = g_xq + (size_t)blockIdx.y * BM * KDIM;
    const __nv_bfloat16* gB = g_wq + (size_t)blockIdx.x * BN * KDIM;

    float acc[4][4][4];
#pragma unroll
    for (int i = 0; i < 4; ++i)
#pragma unroll
        for (int j = 0; j < 4; ++j)
#pragma unroll
            for (int k = 0; k < 4; ++k) acc[i][j][k] = 0.f;

    load_stage(sA[0], sB[0], gA, gB, 0, tid);
    int buf = 0;
    for (int kt = 0; kt < NKITER; ++kt) {
        if (kt + 1 < NKITER) {
            load_stage(sA[buf ^ 1], sB[buf ^ 1], gA, gB, (kt + 1) * BK, tid);
            asm volatile("cp.async.wait_group 1;\n" ::: "memory");
        } else {
            asm volatile("cp.async.wait_group 0;\n" ::: "memory");
        }
        __syncthreads();

#pragma unroll
        for (int ks = 0; ks < 2; ++ks) {
            uint32_t a[4][4];
#pragma unroll
            for (int i = 0; i < 4; ++i) {
                uint32_t addr = smem_u32(
                    &sA[buf][(wm + i * 16 + (lane & 15)) * PITCH + ks * 16 + (lane >> 4) * 8]);
                ldsm_x4(a[i], addr);
            }
            uint32_t b[4][2];
#pragma unroll
            for (int jj = 0; jj < 2; ++jj) {
                int g = lane >> 3;
                int row = wn + jj * 16 + ((g >> 1) << 3) + (lane & 7);
                int col = ks * 16 + ((g & 1) << 3);
                uint32_t r[4];
                ldsm_x4(r, smem_u32(&sB[buf][row * PITCH + col]));
                b[2 * jj][0] = r[0]; b[2 * jj][1] = r[1];
                b[2 * jj + 1][0] = r[2]; b[2 * jj + 1][1] = r[3];
            }
#pragma unroll
            for (int i = 0; i < 4; ++i)
#pragma unroll
                for (int j = 0; j < 4; ++j)
                    mma16816(acc[i][j], a[i], b[j]);
        }
        __syncthreads();
        buf ^= 1;
    }

    float inv = g_scales[2];
    int m0 = blockIdx.y * BM + wm;
    int n0 = blockIdx.x * BN + wn;
#pragma unroll
    for (int i = 0; i < 4; ++i) {
        int m = m0 + i * 16 + (lane >> 2);
#pragma unroll
        for (int j = 0; j < 4; ++j) {
            int n = n0 + j * 8 + ((lane & 3) << 1);
            float b0 = bias[n], b1 = bias[n + 1];
            float2 v0 = make_float2(acc[i][j][0] * inv + b0, acc[i][j][1] * inv + b1);
            float2 v1 = make_float2(acc[i][j][2] * inv + b0, acc[i][j][3] * inv + b1);
            *reinterpret_cast<float2*>(&out[(size_t)m * NDIM + n]) = v0;
            *reinterpret_cast<float2*>(&out[(size_t)(m + 8) * NDIM + n]) = v1;
        }
    }
}

// ---------------- launch ----------------
extern "C" void kernel_launch(void* const* d_in, const int* in_sizes, int n_in,
                              void* d_out, int out_size) {
    const float* x    = (const float*)d_in[0];   // [4,2048,4096]
    const float* w    = (const float*)d_in[1];   // [16384,4096]
    const float* bias = (const float*)d_in[2];   // [16384]
    float* out = (float*)d_out;                  // [4,2048,16384]

    size_t nx4 = (size_t)MDIM * KDIM / 4;
    size_t nw4 = (size_t)NDIM * KDIM / 4;

    init_kernel<<<1, 32>>>();
    amax_kernel<<<1024, 256>>>((const float4*)x, nx4, 0);
    amax_kernel<<<2048, 256>>>((const float4*)w, nw4, 1);
    scales_kernel<<<1, 1>>>();
    quant_kernel<<<2048, 256>>>((const float4*)x, nx4, 0);
    quant_kernel<<<4096, 256>>>((const float4*)w, nw4, 1);

    dim3 grid(NDIM / BN, MDIM / BM);   // (128, 64)
    gemm_kernel<<<grid, 256>>>(bias, out);
}

// round 4
// speedup vs baseline: 1.0460x; 1.0460x over previous
#include <cuda_runtime.h>
#include <cuda_bf16.h>
#include <cstdint>
#include <cstddef>

// Problem dims: x [4,2048,4096] -> M=8192, K=4096; w [16384,4096] -> N=16384
#define MDIM 8192
#define KDIM 4096
#define NDIM 16384
#define MAXV 448.0f
#define EPSV 1e-12f

// ---------------- device scratch ----------------
__device__ unsigned int g_amax_bits[2];
__device__ float g_scales[3];                       // sx, sw, 1/(sx*sw)
__device__ uint8_t g_xq[(size_t)MDIM * KDIM];       // 32 MB e4m3 (scaled domain)
__device__ uint8_t g_wq[(size_t)NDIM * KDIM];       // 64 MB e4m3 (scaled domain)

// ---------------- init / amax / scales ----------------
__global__ void init_kernel() {
    if (threadIdx.x < 2) g_amax_bits[threadIdx.x] = __float_as_uint(EPSV);
}

__global__ void amax_kernel(const float4* __restrict__ p, size_t n4, int slot) {
    float m = 0.f;
    size_t stride = (size_t)gridDim.x * blockDim.x;
    for (size_t i = (size_t)blockIdx.x * blockDim.x + threadIdx.x; i < n4; i += stride) {
        float4 v = p[i];
        m = fmaxf(m, fminf(fabsf(v.x), MAXV));
        m = fmaxf(m, fminf(fabsf(v.y), MAXV));
        m = fmaxf(m, fminf(fabsf(v.z), MAXV));
        m = fmaxf(m, fminf(fabsf(v.w), MAXV));
    }
#pragma unroll
    for (int o = 16; o > 0; o >>= 1) m = fmaxf(m, __shfl_xor_sync(0xffffffffu, m, o));
    if ((threadIdx.x & 31) == 0) atomicMax(&g_amax_bits[slot], __float_as_uint(m));
}

__global__ void scales_kernel() {
    float ax = __uint_as_float(g_amax_bits[0]);
    float aw = __uint_as_float(g_amax_bits[1]);
    float sx = MAXV / ax, sw = MAXV / aw;
    g_scales[0] = sx;
    g_scales[1] = sw;
    g_scales[2] = (1.f / sx) * (1.f / sw);
}

// ---------------- fake-quantize in scaled domain, then pack to e4m3 ----------------
__device__ __forceinline__ float fqs(float v, float scale) {
    float c = fminf(fmaxf(v, -MAXV), MAXV);
    float s = c * scale;                     // |s| <= 448
    float mag = fmaxf(fabsf(s), EPSV);
    int e;
    frexpf(mag, &e);                         // floor(log2(mag)) = e-1
    float r = rintf(ldexpf(mag, 4 - e));     // mag/step, in [8,16], half-to-even
    float q = ldexpf(r, e - 4);              // back to scaled domain (exact)
    return copysignf(q, s);
}

__device__ __forceinline__ uint32_t pack4_e4m3(float a, float b, float c, float d) {
    uint16_t lo, hi;
    asm("cvt.rn.satfinite.e4m3x2.f32 %0, %2, %1;" : "=h"(lo) : "f"(a), "f"(b));
    asm("cvt.rn.satfinite.e4m3x2.f32 %0, %2, %1;" : "=h"(hi) : "f"(c), "f"(d));
    return (uint32_t)lo | ((uint32_t)hi << 16);
}

__global__ void quant_kernel(const float4* __restrict__ in, size_t n4, int slot) {
    uint32_t* outq = (uint32_t*)((slot == 0) ? g_xq : g_wq);
    float s = g_scales[slot];
    size_t stride = (size_t)gridDim.x * blockDim.x;
    for (size_t i = (size_t)blockIdx.x * blockDim.x + threadIdx.x; i < n4; i += stride) {
        float4 v = in[i];
        outq[i] = pack4_e4m3(fqs(v.x, s), fqs(v.y, s), fqs(v.z, s), fqs(v.w, s));
    }
}

// =======================================================================
// FP8 mma.sync GEMM: out = (xq_scaled @ wq_scaled^T) * inv + bias
// CTA 128x128, BK=64 fp8, 4-stage cp.async ring, warp tile 64x32
// =======================================================================
#define BM 128
#define BN 128
#define BK 64
#define STAGES 4
#define NKIT (KDIM / BK)            // 64
#define PITCHB 80                   // bytes per smem row (64 data + 16 pad)
#define TILE_B (128 * PITCHB)       // 10240 per operand
#define STAGE_B (2 * TILE_B)        // 20480
#define SMEM_TOT (STAGES * STAGE_B) // 81920

__device__ __forceinline__ uint32_t smem_u32(const void* p) {
    return (uint32_t)__cvta_generic_to_shared(p);
}
__device__ __forceinline__ void cp16s(uint32_t dst, const void* src) {
    asm volatile("cp.async.cg.shared.global [%0], [%1], 16;\n" :: "r"(dst), "l"(src));
}
__device__ __forceinline__ void ldsm_x4(uint32_t* r, uint32_t addr) {
    asm volatile("ldmatrix.sync.aligned.m8n8.x4.shared.b16 {%0,%1,%2,%3}, [%4];\n"
                 : "=r"(r[0]), "=r"(r[1]), "=r"(r[2]), "=r"(r[3]) : "r"(addr));
}
__device__ __forceinline__ void mma_fp8(float* c, const uint32_t* a, const uint32_t* b) {
    asm volatile("mma.sync.aligned.m16n8k32.row.col.f32.e4m3.e4m3.f32 "
                 "{%0,%1,%2,%3}, {%4,%5,%6,%7}, {%8,%9}, {%0,%1,%2,%3};\n"
                 : "+f"(c[0]), "+f"(c[1]), "+f"(c[2]), "+f"(c[3])
                 : "r"(a[0]), "r"(a[1]), "r"(a[2]), "r"(a[3]), "r"(b[0]), "r"(b[1]));
}

__device__ __forceinline__ void load_stage(uint8_t* smem, int s,
                                           const uint8_t* __restrict__ gA,
                                           const uint8_t* __restrict__ gB,
                                           int k0, int tid) {
    uint32_t stA = smem_u32(smem + (size_t)s * STAGE_B);
    uint32_t stB = stA + TILE_B;
#pragma unroll
    for (int j = 0; j < 2; ++j) {
        int chunk = j * 256 + tid;          // 512 chunks of 16B per operand
        int r = chunk >> 2;
        int c = (chunk & 3) * 16;           // byte col
        cp16s(stA + r * PITCHB + c, gA + (size_t)r * KDIM + k0 + c);
        cp16s(stB + r * PITCHB + c, gB + (size_t)r * KDIM + k0 + c);
    }
    asm volatile("cp.async.commit_group;\n" ::: "memory");
}

__global__ void __launch_bounds__(256, 2)
gemm_fp8_kernel(const float* __restrict__ bias, float* __restrict__ out) {
    extern __shared__ uint8_t smem[];

    int tid = threadIdx.x;
    int lane = tid & 31, warp = tid >> 5;
    int wm = (warp >> 2) * 64;   // warps 2(M) x 4(N); warp tile 64x32
    int wn = (warp & 3) * 32;
    int mblk = blockIdx.x, nblk = blockIdx.y;

    const uint8_t* gA = g_xq + (size_t)mblk * BM * KDIM;
    const uint8_t* gB = g_wq + (size_t)nblk * BN * KDIM;

    float acc[4][4][4];
#pragma unroll
    for (int i = 0; i < 4; ++i)
#pragma unroll
        for (int j = 0; j < 4; ++j)
#pragma unroll
            for (int k = 0; k < 4; ++k) acc[i][j][k] = 0.f;

    // prologue: fill 3 stages
    load_stage(smem, 0, gA, gB, 0, tid);
    load_stage(smem, 1, gA, gB, BK, tid);
    load_stage(smem, 2, gA, gB, 2 * BK, tid);

    for (int kt = 0; kt < NKIT; ++kt) {
        asm volatile("cp.async.wait_group 2;\n" ::: "memory");
        __syncthreads();
        if (kt + 3 < NKIT)
            load_stage(smem, (kt + 3) & (STAGES - 1), gA, gB, (kt + 3) * BK, tid);

        uint32_t stA = smem_u32(smem + (size_t)(kt & (STAGES - 1)) * STAGE_B);
        uint32_t stB = stA + TILE_B;
#pragma unroll
        for (int ks = 0; ks < 2; ++ks) {          // two k32 steps per BK=64
            uint32_t a[4][4];
#pragma unroll
            for (int i = 0; i < 4; ++i) {
                uint32_t addr = stA + (wm + i * 16 + (lane & 15)) * PITCHB
                                    + ks * 32 + (lane >> 4) * 16;
                ldsm_x4(a[i], addr);
            }
            uint32_t b[4][2];
#pragma unroll
            for (int jj = 0; jj < 2; ++jj) {
                int g = lane >> 3;
                int row = wn + jj * 16 + ((g >> 1) << 3) + (lane & 7);
                int col = ks * 32 + ((g & 1) << 4);
                uint32_t r[4];
                ldsm_x4(r, stB + row * PITCHB + col);
                b[2 * jj][0] = r[0]; b[2 * jj][1] = r[1];
                b[2 * jj + 1][0] = r[2]; b[2 * jj + 1][1] = r[3];
            }
#pragma unroll
            for (int i = 0; i < 4; ++i)
#pragma unroll
                for (int j = 0; j < 4; ++j)
                    mma_fp8(acc[i][j], a[i], b[j]);
        }
        __syncthreads();
    }

    float inv = g_scales[2];
    int m0 = mblk * BM + wm;
    int n0 = nblk * BN + wn;
#pragma unroll
    for (int i = 0; i < 4; ++i) {
        int m = m0 + i * 16 + (lane >> 2);
#pragma unroll
        for (int j = 0; j < 4; ++j) {
            int n = n0 + j * 8 + ((lane & 3) << 1);
            float b0 = bias[n], b1 = bias[n + 1];
            float2 v0 = make_float2(acc[i][j][0] * inv + b0, acc[i][j][1] * inv + b1);
            float2 v1 = make_float2(acc[i][j][2] * inv + b0, acc[i][j][3] * inv + b1);
            *reinterpret_cast<float2*>(&out[(size_t)m * NDIM + n]) = v0;
            *reinterpret_cast<float2*>(&out[(size_t)(m + 8) * NDIM + n]) = v1;
        }
    }
}

// ---------------- launch ----------------
extern "C" void kernel_launch(void* const* d_in, const int* in_sizes, int n_in,
                              void* d_out, int out_size) {
    const float* x    = (const float*)d_in[0];
    const float* w    = (const float*)d_in[1];
    const float* bias = (const float*)d_in[2];
    float* out = (float*)d_out;

    size_t nx4 = (size_t)MDIM * KDIM / 4;
    size_t nw4 = (size_t)NDIM * KDIM / 4;

    init_kernel<<<1, 32>>>();
    amax_kernel<<<1024, 256>>>((const float4*)x, nx4, 0);
    amax_kernel<<<2048, 256>>>((const float4*)w, nw4, 1);
    scales_kernel<<<1, 1>>>();
    quant_kernel<<<2048, 256>>>((const float4*)x, nx4, 0);
    quant_kernel<<<4096, 256>>>((const float4*)w, nw4, 1);

    static bool attr_done = false;
    if (!attr_done) {
        cudaFuncSetAttribute(gemm_fp8_kernel,
                             cudaFuncAttributeMaxDynamicSharedMemorySize, SMEM_TOT);
        attr_done = true;
    }
    dim3 grid(MDIM / BM, NDIM / BN);   // (64, 128): M fastest; A panel (32MB) L2-resident
    gemm_fp8_kernel<<<grid, 256, SMEM_TOT>>>(bias, out);
}

// round 5
// speedup vs baseline: 1.1989x; 1.1462x over previous
#include <cuda_runtime.h>
#include <cuda_bf16.h>
#include <cstdint>
#include <cstddef>

// Problem dims: x [4,2048,4096] -> M=8192, K=4096; w [16384,4096] -> N=16384
#define MDIM 8192
#define KDIM 4096
#define NDIM 16384
#define MAXV 448.0f
#define EPSV 1e-12f

// ---------------- device scratch ----------------
__device__ unsigned int g_amax_bits[2];
__device__ float g_scales[3];                       // sx, sw, 1/(sx*sw)
__device__ uint8_t g_xq[(size_t)MDIM * KDIM];       // 32 MB e4m3 (scaled domain)
__device__ uint8_t g_wq[(size_t)NDIM * KDIM];       // 64 MB e4m3 (scaled domain)

// ---------------- init / amax / scales ----------------
__global__ void init_kernel() {
    if (threadIdx.x < 2) g_amax_bits[threadIdx.x] = __float_as_uint(EPSV);
}

__global__ void amax_kernel(const float4* __restrict__ p, size_t n4, int slot) {
    float m = 0.f;
    size_t stride = (size_t)gridDim.x * blockDim.x;
    for (size_t i = (size_t)blockIdx.x * blockDim.x + threadIdx.x; i < n4; i += stride) {
        float4 v = p[i];
        m = fmaxf(m, fminf(fabsf(v.x), MAXV));
        m = fmaxf(m, fminf(fabsf(v.y), MAXV));
        m = fmaxf(m, fminf(fabsf(v.z), MAXV));
        m = fmaxf(m, fminf(fabsf(v.w), MAXV));
    }
#pragma unroll
    for (int o = 16; o > 0; o >>= 1) m = fmaxf(m, __shfl_xor_sync(0xffffffffu, m, o));
    if ((threadIdx.x & 31) == 0) atomicMax(&g_amax_bits[slot], __float_as_uint(m));
}

__global__ void scales_kernel() {
    float ax = __uint_as_float(g_amax_bits[0]);
    float aw = __uint_as_float(g_amax_bits[1]);
    float sx = MAXV / ax, sw = MAXV / aw;
    g_scales[0] = sx;
    g_scales[1] = sw;
    g_scales[2] = (1.f / sx) * (1.f / sw);
}

// ---------------- fake-quantize in scaled domain, pack to e4m3 ----------------
__device__ __forceinline__ float fqs(float v, float scale) {
    float c = fminf(fmaxf(v, -MAXV), MAXV);
    float s = c * scale;                     // |s| <= 448
    float mag = fmaxf(fabsf(s), EPSV);
    int e;
    frexpf(mag, &e);                         // floor(log2(mag)) = e-1
    float r = rintf(ldexpf(mag, 4 - e));     // mag/step in [8,16], half-to-even
    float q = ldexpf(r, e - 4);              // exact
    return copysignf(q, s);
}

__device__ __forceinline__ uint32_t pack4_e4m3(float a, float b, float c, float d) {
    uint16_t lo, hi;
    asm("cvt.rn.satfinite.e4m3x2.f32 %0, %2, %1;" : "=h"(lo) : "f"(a), "f"(b));
    asm("cvt.rn.satfinite.e4m3x2.f32 %0, %2, %1;" : "=h"(hi) : "f"(c), "f"(d));
    return (uint32_t)lo | ((uint32_t)hi << 16);
}

#define XBLOCKS 2048
#define WBLOCKS 4096
// fused: one launch quantizes both tensors (keeps GEMM at launch #6 for ncu -s 5)
__global__ void quant_fused_kernel(const float4* __restrict__ x, const float4* __restrict__ w) {
    int seg = (blockIdx.x < XBLOCKS) ? 0 : 1;
    const float4* in = seg ? w : x;
    uint32_t* outq = (uint32_t*)(seg ? g_wq : g_xq);
    size_t n4 = seg ? ((size_t)NDIM * KDIM / 4) : ((size_t)MDIM * KDIM / 4);
    int b = seg ? (blockIdx.x - XBLOCKS) : blockIdx.x;
    size_t nb = seg ? WBLOCKS : XBLOCKS;
    float s = g_scales[seg];
    size_t stride = nb * blockDim.x;
    for (size_t i = (size_t)b * blockDim.x + threadIdx.x; i < n4; i += stride) {
        float4 v = in[i];
        outq[i] = pack4_e4m3(fqs(v.x, s), fqs(v.y, s), fqs(v.z, s), fqs(v.w, s));
    }
}

// =======================================================================
// FP8 mma.sync GEMM: out = (xq_s @ wq_s^T) * inv + bias
// CTA 128x128, 4 warps (2x2), warp tile 64x64, BK=64, 4-stage cp.async
// =======================================================================
#define BM 128
#define BN 128
#define BK 64
#define STAGES 4
#define NKIT (KDIM / BK)            // 64
#define PITCHB 80                   // bytes/smem row (64 data + 16 pad): conflict-free ldmatrix
#define TILE_B (128 * PITCHB)       // 10240 per operand
#define STAGE_B (2 * TILE_B)        // 20480
#define SMEM_TOT (STAGES * STAGE_B) // 81920

__device__ __forceinline__ uint32_t smem_u32(const void* p) {
    return (uint32_t)__cvta_generic_to_shared(p);
}
__device__ __forceinline__ void cp16s(uint32_t dst, const void* src) {
    asm volatile("cp.async.cg.shared.global [%0], [%1], 16;\n" :: "r"(dst), "l"(src));
}
__device__ __forceinline__ void ldsm_x4(uint32_t* r, uint32_t addr) {
    asm volatile("ldmatrix.sync.aligned.m8n8.x4.shared.b16 {%0,%1,%2,%3}, [%4];\n"
                 : "=r"(r[0]), "=r"(r[1]), "=r"(r[2]), "=r"(r[3]) : "r"(addr));
}
__device__ __forceinline__ void mma_fp8(float* c, const uint32_t* a, const uint32_t* b) {
    asm volatile("mma.sync.aligned.m16n8k32.row.col.f32.e4m3.e4m3.f32 "
                 "{%0,%1,%2,%3}, {%4,%5,%6,%7}, {%8,%9}, {%0,%1,%2,%3};\n"
                 : "+f"(c[0]), "+f"(c[1]), "+f"(c[2]), "+f"(c[3])
                 : "r"(a[0]), "r"(a[1]), "r"(a[2]), "r"(a[3]), "r"(b[0]), "r"(b[1]));
}

__device__ __forceinline__ void load_stage(uint8_t* smem, int s,
                                           const uint8_t* __restrict__ gA,
                                           const uint8_t* __restrict__ gB,
                                           int k0, int tid) {
    uint32_t stA = smem_u32(smem + (size_t)s * STAGE_B);
    uint32_t stB = stA + TILE_B;
#pragma unroll
    for (int j = 0; j < 8; ++j) {
        int chunk = j * 128 + tid;          // 0..1023; first 512 = A, rest = B
        if (j < 4) {
            int r = chunk >> 2, c = (chunk & 3) * 16;
            cp16s(stA + r * PITCHB + c, gA + (size_t)r * KDIM + k0 + c);
        } else {
            int bc = chunk - 512;
            int r = bc >> 2, c = (bc & 3) * 16;
            cp16s(stB + r * PITCHB + c, gB + (size_t)r * KDIM + k0 + c);
        }
    }
    asm volatile("cp.async.commit_group;\n" ::: "memory");
}

__global__ void __launch_bounds__(128, 2)
gemm_fp8_kernel(const float* __restrict__ bias, float* __restrict__ out) {
    extern __shared__ uint8_t smem[];

    int tid = threadIdx.x;
    int lane = tid & 31, warp = tid >> 5;
    int wm = (warp >> 1) * 64;   // warps 2(M) x 2(N); warp tile 64x64
    int wn = (warp & 1) * 64;
    int mblk = blockIdx.x, nblk = blockIdx.y;

    const uint8_t* gA = g_xq + (size_t)mblk * BM * KDIM;
    const uint8_t* gB = g_wq + (size_t)nblk * BN * KDIM;

    float acc[4][8][4];
#pragma unroll
    for (int i = 0; i < 4; ++i)
#pragma unroll
        for (int j = 0; j < 8; ++j)
#pragma unroll
            for (int k = 0; k < 4; ++k) acc[i][j][k] = 0.f;

    load_stage(smem, 0, gA, gB, 0, tid);
    load_stage(smem, 1, gA, gB, BK, tid);
    load_stage(smem, 2, gA, gB, 2 * BK, tid);

    for (int kt = 0; kt < NKIT; ++kt) {
        asm volatile("cp.async.wait_group 2;\n" ::: "memory");
        __syncthreads();
        if (kt + 3 < NKIT)
            load_stage(smem, (kt + 3) & (STAGES - 1), gA, gB, (kt + 3) * BK, tid);

        uint32_t stA = smem_u32(smem + (size_t)(kt & (STAGES - 1)) * STAGE_B);
        uint32_t stB = stA + TILE_B;
#pragma unroll
        for (int ks = 0; ks < 2; ++ks) {          // two k32 steps per BK=64
            uint32_t a[4][4];
#pragma unroll
            for (int i = 0; i < 4; ++i) {
                uint32_t addr = stA + (wm + i * 16 + (lane & 15)) * PITCHB
                                    + ks * 32 + (lane >> 4) * 16;
                ldsm_x4(a[i], addr);
            }
            uint32_t b[8][2];
#pragma unroll
            for (int jj = 0; jj < 4; ++jj) {
                int g = lane >> 3;
                int row = wn + jj * 16 + ((g >> 1) << 3) + (lane & 7);
                int col = ks * 32 + ((g & 1) << 4);
                uint32_t r[4];
                ldsm_x4(r, stB + row * PITCHB + col);
                b[2 * jj][0] = r[0]; b[2 * jj][1] = r[1];
                b[2 * jj + 1][0] = r[2]; b[2 * jj + 1][1] = r[3];
            }
#pragma unroll
            for (int i = 0; i < 4; ++i)
#pragma unroll
                for (int j = 0; j < 8; ++j)
                    mma_fp8(acc[i][j], a[i], b[j]);
        }
        __syncthreads();
    }

    float inv = g_scales[2];
    int m0 = mblk * BM + wm;
    int n0 = nblk * BN + wn;
#pragma unroll
    for (int i = 0; i < 4; ++i) {
        int m = m0 + i * 16 + (lane >> 2);
#pragma unroll
        for (int j = 0; j < 8; ++j) {
            int n = n0 + j * 8 + ((lane & 3) << 1);
            float b0 = bias[n], b1 = bias[n + 1];
            float2 v0 = make_float2(acc[i][j][0] * inv + b0, acc[i][j][1] * inv + b1);
            float2 v1 = make_float2(acc[i][j][2] * inv + b0, acc[i][j][3] * inv + b1);
            *reinterpret_cast<float2*>(&out[(size_t)m * NDIM + n]) = v0;
            *reinterpret_cast<float2*>(&out[(size_t)(m + 8) * NDIM + n]) = v1;
        }
    }
}

// ---------------- launch (6 launches: ncu -s 5 captures the GEMM) ----------------
extern "C" void kernel_launch(void* const* d_in, const int* in_sizes, int n_in,
                              void* d_out, int out_size) {
    const float* x    = (const float*)d_in[0];
    const float* w    = (const float*)d_in[1];
    const float* bias = (const float*)d_in[2];
    float* out = (float*)d_out;

    size_t nx4 = (size_t)MDIM * KDIM / 4;
    size_t nw4 = (size_t)NDIM * KDIM / 4;

    init_kernel<<<1, 32>>>();
    amax_kernel<<<1024, 256>>>((const float4*)x, nx4, 0);
    amax_kernel<<<2048, 256>>>((const float4*)w, nw4, 1);
    scales_kernel<<<1, 1>>>();
    quant_fused_kernel<<<XBLOCKS + WBLOCKS, 256>>>((const float4*)x, (const float4*)w);

    static bool attr_done = false;
    if (!attr_done) {
        cudaFuncSetAttribute(gemm_fp8_kernel,
                             cudaFuncAttributeMaxDynamicSharedMemorySize, SMEM_TOT);
        attr_done = true;
    }
    dim3 grid(MDIM / BM, NDIM / BN);   // (64, 128): M fastest; A panel (32MB) L2-resident
    gemm_fp8_kernel<<<grid, 128, SMEM_TOT>>>(bias, out);
}